// round 15
// baseline (speedup 1.0000x reference)
#include <cuda_runtime.h>
#include <math.h>

// Problem constants
#define BB 16
#define SS 512
#define DD 512
#define HH 8
#define HD 64
#define LL 6
#define FF 2048
#define VV 10000
#define MM (BB*SS)          // 8192 rows
#define NTOT (MM*DD)        // 4194304
#define K0RANK 3145727u     // floor(0.75*(NTOT-1))
#define K1RANK 3145728u
#define KC 256              // Eigen gebp kc panel size hypothesis

// ---------------- device scratch ----------------
__device__ float g_x[NTOT];
__device__ float g_qkv[MM*3*DD];
__device__ float g_ctx[NTOT];
__device__ float g_tmp[NTOT];
__device__ float g_ff[MM*FF];
__device__ double g_part[1024];
__device__ double g_sumsq;
__device__ unsigned g_h1[65536];
__device__ unsigned g_h2[2][65536];
__device__ unsigned g_sel[4];   // bin0, before0, bin1, before1
__device__ float g_thr;

// ---------------- embedding ----------------
__global__ void embed_kernel(const int* __restrict__ src, const float* __restrict__ emb,
                             const float* __restrict__ pos, float* __restrict__ x, float sqrtD) {
    int i = blockIdx.x * blockDim.x + threadIdx.x;
    if (i >= NTOT) return;
    int t = i >> 9, d = i & 511, s = t & 511;
    float e = emb[(size_t)src[t] * DD + d];
    x[i] = __fadd_rn(__fmul_rn(e, sqrtD), pos[(size_t)s * DD + d]);
}

// ---------------- GEMM: C[M,N] = A[M,K] * W[N,K]^T (+bias,+res,relu) ----------------
// Eigen gebp hypothesis: K split into kc=256 panels; within a panel serial
// ascending-k FMA (registers); panels folded left-associative (C mem += panel).
// RESMODE 0: acc+bias ; 1: (res+acc)+bias ; 2: res+(acc+bias)
template<int RELU, int RESMODE, bool BOUND>
__global__ __launch_bounds__(256)
void gemm_kernel(const float* __restrict__ A, const float* __restrict__ W,
                 const float* __restrict__ bias, const float* __restrict__ R,
                 float* __restrict__ C, int M, int N, int K) {
    __shared__ float As[16][132];
    __shared__ float Bs[16][132];
    const int tid = threadIdx.x;
    const int row0 = blockIdx.y * 128;
    const int col0 = blockIdx.x * 128;
    const int ty = tid >> 4, tx = tid & 15;

    float accT[8][8], accP[8][8];
#pragma unroll
    for (int i = 0; i < 8; i++)
#pragma unroll
        for (int j = 0; j < 8; j++) { accT[i][j] = 0.f; accP[i][j] = 0.f; }

    for (int kt = 0; kt < K; kt += 16) {
#pragma unroll
        for (int f = tid; f < 512; f += 256) {
            int r = f >> 2, c4 = (f & 3) << 2;
            float4 v = *(const float4*)(A + (size_t)(row0 + r) * K + kt + c4);
            As[c4 + 0][r] = v.x; As[c4 + 1][r] = v.y;
            As[c4 + 2][r] = v.z; As[c4 + 3][r] = v.w;
        }
#pragma unroll
        for (int f = tid; f < 512; f += 256) {
            int r = f >> 2, c4 = (f & 3) << 2;
            int gr = col0 + r;
            float4 v = make_float4(0.f, 0.f, 0.f, 0.f);
            if (!BOUND || gr < N) v = *(const float4*)(W + (size_t)gr * K + kt + c4);
            Bs[c4 + 0][r] = v.x; Bs[c4 + 1][r] = v.y;
            Bs[c4 + 2][r] = v.z; Bs[c4 + 3][r] = v.w;
        }
        __syncthreads();
#pragma unroll
        for (int k = 0; k < 16; k++) {
            float a[8], b[8];
#pragma unroll
            for (int i = 0; i < 8; i++) a[i] = As[k][ty * 8 + i];
#pragma unroll
            for (int j = 0; j < 8; j++) b[j] = Bs[k][tx * 8 + j];
#pragma unroll
            for (int i = 0; i < 8; i++)
#pragma unroll
                for (int j = 0; j < 8; j++) accP[i][j] = fmaf(a[i], b[j], accP[i][j]);
        }
        __syncthreads();
        // end of kc panel: fold into memory-accumulator (left-assoc)
        if (((kt + 16) & (KC - 1)) == 0) {
#pragma unroll
            for (int i = 0; i < 8; i++)
#pragma unroll
                for (int j = 0; j < 8; j++) {
                    accT[i][j] = __fadd_rn(accT[i][j], accP[i][j]);
                    accP[i][j] = 0.f;
                }
        }
    }

#pragma unroll
    for (int i = 0; i < 8; i++) {
        int r = row0 + ty * 8 + i;
#pragma unroll
        for (int j = 0; j < 8; j++) {
            int c = col0 + tx * 8 + j;
            if (BOUND && c >= N) continue;
            float v;
            if (RESMODE == 0) {
                v = __fadd_rn(accT[i][j], bias[c]);
            } else if (RESMODE == 1) {
                v = __fadd_rn(__fadd_rn(R[(size_t)r * N + c], accT[i][j]), bias[c]);
            } else {
                v = __fadd_rn(R[(size_t)r * N + c], __fadd_rn(accT[i][j], bias[c]));
            }
            if (RELU) v = fmaxf(v, 0.f);
            C[(size_t)r * N + c] = v;
        }
    }
}

// ---------------- row-reduce tree (R13 form; reduce form shown irrelevant) ----------------
template<typename F>
__device__ __forceinline__ float xla_tree512(F val) {
    float S[8];
#pragma unroll
    for (int w = 0; w < 8; w++) {
        int base = w * 64;
        float p[32];
#pragma unroll
        for (int t = 0; t < 32; t++)
            p[t] = __fadd_rn(val(base + 2 * t), val(base + 2 * t + 1));
#pragma unroll
        for (int t = 0; t < 16; t++) p[t] = __fadd_rn(p[t], p[t + 16]);
#pragma unroll
        for (int t = 0; t < 8; t++)  p[t] = __fadd_rn(p[t], p[t + 8]);
#pragma unroll
        for (int t = 0; t < 4; t++)  p[t] = __fadd_rn(p[t], p[t + 4]);
        float d0 = __fadd_rn(p[0], p[2]);
        float d1 = __fadd_rn(p[1], p[3]);
        S[w] = __fadd_rn(d0, d1);
    }
    float e0 = __fadd_rn(S[0], S[4]);
    float e1 = __fadd_rn(S[1], S[5]);
    float e2 = __fadd_rn(S[2], S[6]);
    float e3 = __fadd_rn(S[3], S[7]);
    return __fadd_rn(__fadd_rn(e0, e2), __fadd_rn(e1, e3));
}

// ---------------- attention ----------------
#define QPAD 68
#define PPAD 513
#define SM_Q   0
#define SM_KV  (64*QPAD)
#define SM_P   (SM_KV + 32*QPAD)
#define SM_M   (SM_P + 64*PPAD)
#define SM_S   (SM_M + 64)
#define ATTN_SMEM_BYTES ((SM_S + 64)*4)

__global__ __launch_bounds__(256)
void attn_kernel(const float* __restrict__ qkv, float* __restrict__ ctx) {
    extern __shared__ float sm[];
    float* Qs = sm + SM_Q;
    float* KV = sm + SM_KV;
    float* P  = sm + SM_P;
    float* Mrow = sm + SM_M;
    float* Srow = sm + SM_S;

    const int tid = threadIdx.x;
    const int b = blockIdx.z, h = blockIdx.y, q0 = blockIdx.x * 64;
    const float* base = qkv + (size_t)b * SS * (3 * DD);
    const int hoff = h * HD;
    const int tq = tid >> 4, td = tid & 15;

    // load Q tile [64][64]
    for (int f = tid; f < 64 * 16; f += 256) {
        int r = f >> 4, c4 = (f & 15) << 2;
        float4 v = *(const float4*)(base + (size_t)(q0 + r) * (3 * DD) + hoff + c4);
        Qs[r * QPAD + c4] = v.x; Qs[r * QPAD + c4 + 1] = v.y;
        Qs[r * QPAD + c4 + 2] = v.z; Qs[r * QPAD + c4 + 3] = v.w;
    }

    // ---- scores t=(q.k)*0.125 (K=64 -> single panel, serial FMA; /8 exact) ----
    for (int c0 = 0; c0 < SS; c0 += 32) {
        __syncthreads();
        for (int f = tid; f < 32 * 16; f += 256) {
            int r = f >> 4, c4 = (f & 15) << 2;
            const float* p = base + (size_t)(c0 + r) * (3 * DD) + hoff + c4 + DD; // K
            float4 kv = *(const float4*)p;
            KV[r * QPAD + c4] = kv.x; KV[r * QPAD + c4 + 1] = kv.y;
            KV[r * QPAD + c4 + 2] = kv.z; KV[r * QPAD + c4 + 3] = kv.w;
        }
        __syncthreads();
        float s[4][2];
#pragma unroll
        for (int i = 0; i < 4; i++) { s[i][0] = 0.f; s[i][1] = 0.f; }
#pragma unroll
        for (int d = 0; d < 64; d++) {
            float qa[4], kb[2];
#pragma unroll
            for (int i = 0; i < 4; i++) qa[i] = Qs[(tq * 4 + i) * QPAD + d];
            kb[0] = KV[(td * 2 + 0) * QPAD + d];
            kb[1] = KV[(td * 2 + 1) * QPAD + d];
#pragma unroll
            for (int i = 0; i < 4; i++) {
                s[i][0] = fmaf(qa[i], kb[0], s[i][0]);
                s[i][1] = fmaf(qa[i], kb[1], s[i][1]);
            }
        }
#pragma unroll
        for (int i = 0; i < 4; i++) {
            P[(tq * 4 + i) * PPAD + c0 + td * 2 + 0] = __fmul_rn(s[i][0], 0.125f);
            P[(tq * 4 + i) * PPAD + c0 + td * 2 + 1] = __fmul_rn(s[i][1], 0.125f);
        }
    }
    __syncthreads();

    // ---- rowmax (exact; order-free) ----
    {
        int r = tid >> 2, c4 = tid & 3;
        float m = -3.402823466e38f;
        for (int k = c4; k < 512; k += 4) m = fmaxf(m, P[r * PPAD + k]);
        KV[tid] = m;
        __syncthreads();
        if (tid < 64)
            Mrow[tid] = fmaxf(fmaxf(KV[tid * 4 + 0], KV[tid * 4 + 1]),
                              fmaxf(KV[tid * 4 + 2], KV[tid * 4 + 3]));
        __syncthreads();
    }

    // ---- exp ----
    {
        int r = tid >> 2, c4 = tid & 3;
        float m = Mrow[r];
        for (int k = c4; k < 512; k += 4)
            P[r * PPAD + k] = expf(__fsub_rn(P[r * PPAD + k], m));
    }
    __syncthreads();

    // ---- row sum ----
    if (tid < 64) {
        const float* row = P + tid * PPAD;
        Srow[tid] = xla_tree512([&](int i) { return row[i]; });
    }
    __syncthreads();

    // ---- divide: w = e / sum ----
    for (int idx = tid; idx < 64 * 512; idx += 256) {
        int r = idx >> 9, k = idx & 511;
        P[r * PPAD + k] = __fdiv_rn(P[r * PPAD + k], Srow[r]);
    }

    // ---- ctx = w @ V: K=512 -> 2 kc-panels of 256, panels folded left-assoc ----
    float OT[4][4], OP[4][4];
#pragma unroll
    for (int i = 0; i < 4; i++)
#pragma unroll
        for (int j = 0; j < 4; j++) { OT[i][j] = 0.f; OP[i][j] = 0.f; }

    for (int c0 = 0; c0 < SS; c0 += 32) {
        __syncthreads();
        for (int f = tid; f < 32 * 16; f += 256) {
            int r = f >> 4, c4 = (f & 15) << 2;
            const float* p = base + (size_t)(c0 + r) * (3 * DD) + hoff + c4 + 2 * DD; // V
            float4 vv = *(const float4*)p;
            KV[r * QPAD + c4] = vv.x; KV[r * QPAD + c4 + 1] = vv.y;
            KV[r * QPAD + c4 + 2] = vv.z; KV[r * QPAD + c4 + 3] = vv.w;
        }
        __syncthreads();
#pragma unroll
        for (int k = 0; k < 32; k++) {
            float pv[4], vv[4];
#pragma unroll
            for (int i = 0; i < 4; i++) pv[i] = P[(tq * 4 + i) * PPAD + c0 + k];
#pragma unroll
            for (int j = 0; j < 4; j++) vv[j] = KV[k * QPAD + td * 4 + j];
#pragma unroll
            for (int i = 0; i < 4; i++)
#pragma unroll
                for (int j = 0; j < 4; j++) OP[i][j] = fmaf(pv[i], vv[j], OP[i][j]);
        }
        if (((c0 + 32) & (KC - 1)) == 0) {
#pragma unroll
            for (int i = 0; i < 4; i++)
#pragma unroll
                for (int j = 0; j < 4; j++) {
                    OT[i][j] = __fadd_rn(OT[i][j], OP[i][j]);
                    OP[i][j] = 0.f;
                }
        }
    }

#pragma unroll
    for (int i = 0; i < 4; i++) {
        size_t row = (size_t)(b * SS + q0 + tq * 4 + i) * DD + hoff;
#pragma unroll
        for (int j = 0; j < 4; j++) ctx[row + td * 4 + j] = OT[i][j];
    }
}

// ---------------- layernorm: tree reduces + rsqrtf (approx, matched evidence) ----------------
__global__ __launch_bounds__(256)
void ln_kernel(const float* __restrict__ in, float* __restrict__ out,
               const float* __restrict__ gs, const float* __restrict__ gb) {
    int row = blockIdx.x * 256 + threadIdx.x;
    if (row >= MM) return;
    const float* x = in + (size_t)row * DD;

    float s = xla_tree512([&](int i) { return x[i]; });
    float mean = __fmul_rn(s, 1.0f / 512.0f);

    float q = xla_tree512([&](int i) {
        float d = __fsub_rn(x[i], mean);
        return __fmul_rn(d, d);
    });
    float var = __fmul_rn(q, 1.0f / 512.0f);
    float r = rsqrtf(__fadd_rn(var, 1e-5f));

    float* o = out + (size_t)row * DD;
#pragma unroll 4
    for (int c = 0; c < DD; c++) {
        float d = __fsub_rn(x[c], mean);
        o[c] = __fadd_rn(__fmul_rn(__fmul_rn(d, r), gs[c]), gb[c]);
    }
}

// ---------------- triad resonance ----------------
__global__ void zero_kernel() {
    int i = blockIdx.x * blockDim.x + threadIdx.x;
    if (i < 65536) g_h1[i] = 0u;
    if (i < 131072) ((unsigned*)g_h2)[i] = 0u;
}

__global__ __launch_bounds__(256)
void ss1_kernel(const float* __restrict__ x) {
    double acc = 0.0;
    for (int i = blockIdx.x * blockDim.x + threadIdx.x; i < NTOT; i += gridDim.x * blockDim.x) {
        double v = (double)x[i];
        acc = fma(v, v, acc);
    }
#pragma unroll
    for (int o = 16; o; o >>= 1) acc += __shfl_xor_sync(0xffffffffu, acc, o);
    __shared__ double sm[8];
    if ((threadIdx.x & 31) == 0) sm[threadIdx.x >> 5] = acc;
    __syncthreads();
    if (threadIdx.x == 0) {
        double t = 0.0;
        for (int w = 0; w < 8; w++) t += sm[w];
        g_part[blockIdx.x] = t;
    }
}

__global__ __launch_bounds__(256)
void ss2_kernel() {
    int tid = threadIdx.x;
    double a = ((g_part[tid] + g_part[tid + 256]) + (g_part[tid + 512] + g_part[tid + 768]));
#pragma unroll
    for (int o = 16; o; o >>= 1) a += __shfl_xor_sync(0xffffffffu, a, o);
    __shared__ double sm[8];
    if ((tid & 31) == 0) sm[tid >> 5] = a;
    __syncthreads();
    if (tid == 0) {
        double t = 0.0;
        for (int w = 0; w < 8; w++) t += sm[w];
        g_sumsq = t;
    }
}

// g computed identically in every pass: f32 div rounds once, *2048 exact
__device__ __forceinline__ float triad_g(float h) {
    float norm = (float)sqrt(g_sumsq);
    float denom = __fadd_rn(norm, 1e-8f);
    return __fmul_rn(__fdiv_rn(h, denom), 2048.0f);
}

__global__ __launch_bounds__(256)
void hist_hi_kernel(const float* __restrict__ x) {
    for (int i = blockIdx.x * blockDim.x + threadIdx.x; i < NTOT; i += gridDim.x * blockDim.x) {
        unsigned bits = __float_as_uint(triad_g(x[i])) & 0x7fffffffu;
        atomicAdd(&g_h1[bits >> 16], 1u);
    }
}

__global__ __launch_bounds__(256)
void select_hi_kernel() {
    __shared__ unsigned sm[256], pref[256];
    int tid = threadIdx.x;
    int base = tid << 8;
    unsigned local = 0;
    for (int b = 0; b < 256; b++) local += g_h1[base + b];
    sm[tid] = local;
    __syncthreads();
    if (tid == 0) { unsigned c = 0; for (int i = 0; i < 256; i++) { pref[i] = c; c += sm[i]; } }
    __syncthreads();
    unsigned cum = pref[tid];
    for (int b = 0; b < 256; b++) {
        unsigned c = g_h1[base + b];
        if (c) {
            if (K0RANK >= cum && K0RANK < cum + c) { g_sel[0] = (unsigned)(base + b); g_sel[1] = cum; }
            if (K1RANK >= cum && K1RANK < cum + c) { g_sel[2] = (unsigned)(base + b); g_sel[3] = cum; }
        }
        cum += c;
    }
}

__global__ __launch_bounds__(256)
void hist_lo_kernel(const float* __restrict__ x) {
    unsigned b0 = g_sel[0], b1 = g_sel[2];
    for (int i = blockIdx.x * blockDim.x + threadIdx.x; i < NTOT; i += gridDim.x * blockDim.x) {
        unsigned bits = __float_as_uint(triad_g(x[i])) & 0x7fffffffu;
        unsigned hi = bits >> 16;
        if (hi == b0) atomicAdd(&g_h2[0][bits & 0xffffu], 1u);
        else if (hi == b1) atomicAdd(&g_h2[1][bits & 0xffffu], 1u);
    }
}

__global__ __launch_bounds__(256)
void select_lo_kernel() {
    __shared__ unsigned sm[256], pref[256], vb[2];
    int tid = threadIdx.x;
    unsigned b0 = g_sel[0], before0 = g_sel[1], b1 = g_sel[2], before1 = g_sel[3];
    int which1 = (b1 == b0) ? 0 : 1;
    unsigned r0 = K0RANK - before0;
    unsigned r1 = K1RANK - ((which1 == 0) ? before0 : before1);
    for (int pass = 0; pass < 2; pass++) {
        const unsigned* h = g_h2[(pass == 0) ? 0 : which1];
        unsigned target = (pass == 0) ? r0 : r1;
        int base = tid << 8;
        unsigned local = 0;
        for (int b = 0; b < 256; b++) local += h[base + b];
        sm[tid] = local;
        __syncthreads();
        if (tid == 0) { unsigned c = 0; for (int i = 0; i < 256; i++) { pref[i] = c; c += sm[i]; } }
        __syncthreads();
        unsigned cum = pref[tid];
        for (int b = 0; b < 256; b++) {
            unsigned c = h[base + b];
            if (c && target >= cum && target < cum + c) vb[pass] = (unsigned)(base + b);
            cum += c;
        }
        __syncthreads();
    }
    if (tid == 0) {
        float v0 = __uint_as_float((b0 << 16) | vb[0]);
        float v1 = __uint_as_float((((which1 == 0) ? b0 : b1) << 16) | vb[1]);
        // JAX: low*(1-frac) + high*frac, frac=0.25, all f32
        g_thr = __fadd_rn(__fmul_rn(v0, 0.75f), __fmul_rn(v1, 0.25f));
    }
}

__global__ __launch_bounds__(256)
void apply_kernel(float* __restrict__ x, float da, float db) {
    float thr = g_thr;
    for (int i = blockIdx.x * blockDim.x + threadIdx.x; i < NTOT; i += gridDim.x * blockDim.x) {
        float g = triad_g(x[i]);
        x[i] = (fabsf(g) > thr) ? __fmul_rn(__fmul_rn(g, da), db) : 0.0f;
    }
}

// ---------------- host launcher ----------------
extern "C" void kernel_launch(void* const* d_in, const int* in_sizes, int n_in,
                              void* d_out, int out_size) {
    const int*   src    = (const int*)  d_in[0];
    const float* emb    = (const float*)d_in[1];
    const float* pos    = (const float*)d_in[2];
    const float* qkv_w  = (const float*)d_in[3];
    const float* qkv_b  = (const float*)d_in[4];
    const float* attn_ow= (const float*)d_in[5];
    const float* attn_ob= (const float*)d_in[6];
    const float* ln1_s  = (const float*)d_in[7];
    const float* ln1_b  = (const float*)d_in[8];
    const float* ln2_s  = (const float*)d_in[9];
    const float* ln2_b  = (const float*)d_in[10];
    const float* ff1_w  = (const float*)d_in[11];
    const float* ff1_b  = (const float*)d_in[12];
    const float* ff2_w  = (const float*)d_in[13];
    const float* ff2_b  = (const float*)d_in[14];
    const float* head_w = (const float*)d_in[15];
    const float* head_b = (const float*)d_in[16];
    float* out = (float*)d_out;

    float* x_p;   cudaGetSymbolAddress((void**)&x_p,   g_x);
    float* qkv_p; cudaGetSymbolAddress((void**)&qkv_p, g_qkv);
    float* ctx_p; cudaGetSymbolAddress((void**)&ctx_p, g_ctx);
    float* tmp_p; cudaGetSymbolAddress((void**)&tmp_p, g_tmp);
    float* ff_p;  cudaGetSymbolAddress((void**)&ff_p,  g_ff);

    cudaFuncSetAttribute(attn_kernel, cudaFuncAttributeMaxDynamicSharedMemorySize, ATTN_SMEM_BYTES);

    const float sqrtD = (float)sqrt(512.0);
    const float dampA = (float)pow(0.99, 1.0 / 6.0);

    embed_kernel<<<(NTOT + 255) / 256, 256>>>(src, emb, pos, x_p, sqrtD);

    for (int i = 0; i < LL; i++) {
        const float* qw  = qkv_w   + (size_t)i * 3 * DD * DD;
        const float* qb  = qkv_b   + (size_t)i * 3 * DD;
        const float* ow  = attn_ow + (size_t)i * DD * DD;
        const float* ob  = attn_ob + (size_t)i * DD;
        const float* f1w = ff1_w   + (size_t)i * FF * DD;
        const float* f1b = ff1_b   + (size_t)i * FF;
        const float* f2w = ff2_w   + (size_t)i * DD * FF;
        const float* f2b = ff2_b   + (size_t)i * DD;

        gemm_kernel<0, 0, false><<<dim3(12, 64), 256>>>(x_p, qw, qb, nullptr, qkv_p, MM, 3 * DD, DD);
        attn_kernel<<<dim3(SS / 64, HH, BB), 256, ATTN_SMEM_BYTES>>>(qkv_p, ctx_p);
        gemm_kernel<0, 1, false><<<dim3(4, 64), 256>>>(ctx_p, ow, ob, x_p, tmp_p, MM, DD, DD);
        ln_kernel<<<MM / 256, 256>>>(tmp_p, x_p, ln1_s + (size_t)i * DD, ln1_b + (size_t)i * DD);
        gemm_kernel<1, 0, false><<<dim3(16, 64), 256>>>(x_p, f1w, f1b, nullptr, ff_p, MM, FF, DD);
        gemm_kernel<0, 2, false><<<dim3(4, 64), 256>>>(ff_p, f2w, f2b, x_p, tmp_p, MM, DD, FF);
        ln_kernel<<<MM / 256, 256>>>(tmp_p, x_p, ln2_s + (size_t)i * DD, ln2_b + (size_t)i * DD);

        zero_kernel<<<512, 256>>>();
        ss1_kernel<<<1024, 256>>>(x_p);
        ss2_kernel<<<1, 256>>>();
        hist_hi_kernel<<<4096, 256>>>(x_p);
        select_hi_kernel<<<1, 256>>>();
        hist_lo_kernel<<<4096, 256>>>(x_p);
        select_lo_kernel<<<1, 256>>>();
        float dampB = (float)pow(0.99, (double)i / 6.0);
        apply_kernel<<<4096, 256>>>(x_p, dampA, dampB);
    }

    gemm_kernel<0, 0, true><<<dim3((VV + 127) / 128, 64), 256>>>(x_p, head_w, head_b, nullptr, out, MM, VV, DD);
}

// round 16
// speedup vs baseline: 1.0648x; 1.0648x over previous
#include <cuda_runtime.h>
#include <math.h>

// Problem constants
#define BB 16
#define SS 512
#define DD 512
#define HH 8
#define HD 64
#define LL 6
#define FF 2048
#define VV 10000
#define MM (BB*SS)          // 8192 rows
#define NTOT (MM*DD)        // 4194304
#define K0RANK 3145727u     // floor(0.75*(NTOT-1))
#define K1RANK 3145728u
#define KC 256              // Eigen gebp kc panel size (VALIDATED R15)

// ---------------- device scratch ----------------
__device__ float g_x[NTOT];
__device__ float g_qkv[MM*3*DD];
__device__ float g_ctx[NTOT];
__device__ float g_tmp[NTOT];
__device__ float g_ff[MM*FF];
__device__ double g_part[1024];
__device__ double g_sumsq;
__device__ unsigned g_h1[65536];
__device__ unsigned g_h2[2][65536];
__device__ unsigned g_sel[4];   // bin0, before0, bin1, before1
__device__ float g_thr;

// ---------------- embedding ----------------
__global__ void embed_kernel(const int* __restrict__ src, const float* __restrict__ emb,
                             const float* __restrict__ pos, float* __restrict__ x, float sqrtD) {
    int i = blockIdx.x * blockDim.x + threadIdx.x;
    if (i >= NTOT) return;
    int t = i >> 9, d = i & 511, s = t & 511;
    float e = emb[(size_t)src[t] * DD + d];
    x[i] = __fadd_rn(__fmul_rn(e, sqrtD), pos[(size_t)s * DD + d]);
}

// ---------------- GEMM: C[M,N] = A[M,K] * W[N,K]^T (+bias,+res,relu) ----------------
// NUMERICS FROZEN (validated R15): per output element, serial ascending-k FMA in
// kc=256 panels, panels folded left-associative. This version only changes
// scheduling: double-buffered SMEM, register prefetch, ONE barrier per k-tile.
// RESMODE 0: acc+bias ; 1: (res+acc)+bias ; 2: res+(acc+bias)
template<int RELU, int RESMODE, bool BOUND>
__global__ __launch_bounds__(256)
void gemm_kernel(const float* __restrict__ A, const float* __restrict__ W,
                 const float* __restrict__ bias, const float* __restrict__ R,
                 float* __restrict__ C, int M, int N, int K) {
    __shared__ float As[2][16][132];
    __shared__ float Bs[2][16][132];
    const int tid = threadIdx.x;
    const int row0 = blockIdx.y * 128;
    const int col0 = blockIdx.x * 128;
    const int ty = tid >> 4, tx = tid & 15;
    const int lr = tid >> 2;              // 0..63
    const int lc = (tid & 3) << 2;        // 0,4,8,12

    float accT[8][8], accP[8][8];
#pragma unroll
    for (int i = 0; i < 8; i++)
#pragma unroll
        for (int j = 0; j < 8; j++) { accT[i][j] = 0.f; accP[i][j] = 0.f; }

    float4 ra0, ra1, rb0, rb1;

    // global load of k-tile kt into registers (identical values/zero-fill as R15)
    auto gload = [&](int kt) {
        ra0 = *(const float4*)(A + (size_t)(row0 + lr) * K + kt + lc);
        ra1 = *(const float4*)(A + (size_t)(row0 + 64 + lr) * K + kt + lc);
        int gr0 = col0 + lr, gr1 = col0 + 64 + lr;
        rb0 = (!BOUND || gr0 < N) ? *(const float4*)(W + (size_t)gr0 * K + kt + lc)
                                  : make_float4(0.f, 0.f, 0.f, 0.f);
        rb1 = (!BOUND || gr1 < N) ? *(const float4*)(W + (size_t)gr1 * K + kt + lc)
                                  : make_float4(0.f, 0.f, 0.f, 0.f);
    };
    auto stage = [&](int buf) {
        As[buf][lc + 0][lr] = ra0.x; As[buf][lc + 1][lr] = ra0.y;
        As[buf][lc + 2][lr] = ra0.z; As[buf][lc + 3][lr] = ra0.w;
        As[buf][lc + 0][64 + lr] = ra1.x; As[buf][lc + 1][64 + lr] = ra1.y;
        As[buf][lc + 2][64 + lr] = ra1.z; As[buf][lc + 3][64 + lr] = ra1.w;
        Bs[buf][lc + 0][lr] = rb0.x; Bs[buf][lc + 1][lr] = rb0.y;
        Bs[buf][lc + 2][lr] = rb0.z; Bs[buf][lc + 3][lr] = rb0.w;
        Bs[buf][lc + 0][64 + lr] = rb1.x; Bs[buf][lc + 1][64 + lr] = rb1.y;
        Bs[buf][lc + 2][64 + lr] = rb1.z; Bs[buf][lc + 3][64 + lr] = rb1.w;
    };

    gload(0);
    stage(0);
    __syncthreads();

    const int NT = K >> 4;
    for (int t = 0; t < NT; t++) {
        const int cur = t & 1;
        if (t + 1 < NT) gload((t + 1) << 4);
#pragma unroll
        for (int k = 0; k < 16; k++) {
            float a[8], b[8];
#pragma unroll
            for (int i = 0; i < 8; i++) a[i] = As[cur][k][ty * 8 + i];
#pragma unroll
            for (int j = 0; j < 8; j++) b[j] = Bs[cur][k][tx * 8 + j];
#pragma unroll
            for (int i = 0; i < 8; i++)
#pragma unroll
                for (int j = 0; j < 8; j++) accP[i][j] = fmaf(a[i], b[j], accP[i][j]);
        }
        if (t + 1 < NT) stage(cur ^ 1);
        __syncthreads();
        // end of kc panel: fold into total accumulator (left-assoc), as validated
        if ((((t + 1) << 4) & (KC - 1)) == 0) {
#pragma unroll
            for (int i = 0; i < 8; i++)
#pragma unroll
                for (int j = 0; j < 8; j++) {
                    accT[i][j] = __fadd_rn(accT[i][j], accP[i][j]);
                    accP[i][j] = 0.f;
                }
        }
    }

#pragma unroll
    for (int i = 0; i < 8; i++) {
        int r = row0 + ty * 8 + i;
#pragma unroll
        for (int j = 0; j < 8; j++) {
            int c = col0 + tx * 8 + j;
            if (BOUND && c >= N) continue;
            float v;
            if (RESMODE == 0) {
                v = __fadd_rn(accT[i][j], bias[c]);
            } else if (RESMODE == 1) {
                v = __fadd_rn(__fadd_rn(R[(size_t)r * N + c], accT[i][j]), bias[c]);
            } else {
                v = __fadd_rn(R[(size_t)r * N + c], __fadd_rn(accT[i][j], bias[c]));
            }
            if (RELU) v = fmaxf(v, 0.f);
            C[(size_t)r * N + c] = v;
        }
    }
}

// ---------------- row-reduce tree (validated R15 bracketing) ----------------
template<typename F>
__device__ __forceinline__ float xla_tree512(F val) {
    float S[8];
#pragma unroll
    for (int w = 0; w < 8; w++) {
        int base = w * 64;
        float p[32];
#pragma unroll
        for (int t = 0; t < 32; t++)
            p[t] = __fadd_rn(val(base + 2 * t), val(base + 2 * t + 1));
#pragma unroll
        for (int t = 0; t < 16; t++) p[t] = __fadd_rn(p[t], p[t + 16]);
#pragma unroll
        for (int t = 0; t < 8; t++)  p[t] = __fadd_rn(p[t], p[t + 8]);
#pragma unroll
        for (int t = 0; t < 4; t++)  p[t] = __fadd_rn(p[t], p[t + 4]);
        float d0 = __fadd_rn(p[0], p[2]);
        float d1 = __fadd_rn(p[1], p[3]);
        S[w] = __fadd_rn(d0, d1);
    }
    float e0 = __fadd_rn(S[0], S[4]);
    float e1 = __fadd_rn(S[1], S[5]);
    float e2 = __fadd_rn(S[2], S[6]);
    float e3 = __fadd_rn(S[3], S[7]);
    return __fadd_rn(__fadd_rn(e0, e2), __fadd_rn(e1, e3));
}

// ---------------- attention (64-col tiles; same per-element k-order & folds) ----------------
#define QPAD 68
#define PPAD 513
#define SM_Q   0                    // 64*68 = 4352
#define SM_KV  4352                 // 64*68 = 4352
#define SM_P   8704                 // 64*513 = 32832
#define SM_M   41536                // 64
#define SM_S   41600                // 64
#define ATTN_SMEM_BYTES ((41664)*4) // 166656 B

__global__ __launch_bounds__(256)
void attn_kernel(const float* __restrict__ qkv, float* __restrict__ ctx) {
    extern __shared__ float sm[];
    float* Qs = sm + SM_Q;
    float* KV = sm + SM_KV;
    float* P  = sm + SM_P;
    float* Mrow = sm + SM_M;
    float* Srow = sm + SM_S;

    const int tid = threadIdx.x;
    const int b = blockIdx.z, h = blockIdx.y, q0 = blockIdx.x * 64;
    const float* base = qkv + (size_t)b * SS * (3 * DD);
    const int hoff = h * HD;
    const int tq = tid >> 4, td = tid & 15;

    // load Q tile [64][64]
    for (int f = tid; f < 64 * 16; f += 256) {
        int r = f >> 4, c4 = (f & 15) << 2;
        float4 v = *(const float4*)(base + (size_t)(q0 + r) * (3 * DD) + hoff + c4);
        Qs[r * QPAD + c4] = v.x; Qs[r * QPAD + c4 + 1] = v.y;
        Qs[r * QPAD + c4 + 2] = v.z; Qs[r * QPAD + c4 + 3] = v.w;
    }

    // ---- scores t=(q.k)*0.125 (K=64 single panel, serial FMA; /8 exact) ----
    for (int c0 = 0; c0 < SS; c0 += 64) {
        __syncthreads();
        for (int f = tid; f < 64 * 16; f += 256) {
            int r = f >> 4, c4 = (f & 15) << 2;
            const float* p = base + (size_t)(c0 + r) * (3 * DD) + hoff + c4 + DD; // K
            float4 kv = *(const float4*)p;
            KV[r * QPAD + c4] = kv.x; KV[r * QPAD + c4 + 1] = kv.y;
            KV[r * QPAD + c4 + 2] = kv.z; KV[r * QPAD + c4 + 3] = kv.w;
        }
        __syncthreads();
        float s[4][4];
#pragma unroll
        for (int i = 0; i < 4; i++)
#pragma unroll
            for (int j = 0; j < 4; j++) s[i][j] = 0.f;
#pragma unroll
        for (int d = 0; d < 64; d++) {
            float qa[4], kb[4];
#pragma unroll
            for (int i = 0; i < 4; i++) qa[i] = Qs[(tq * 4 + i) * QPAD + d];
#pragma unroll
            for (int j = 0; j < 4; j++) kb[j] = KV[(td * 4 + j) * QPAD + d];
#pragma unroll
            for (int i = 0; i < 4; i++)
#pragma unroll
                for (int j = 0; j < 4; j++) s[i][j] = fmaf(qa[i], kb[j], s[i][j]);
        }
#pragma unroll
        for (int i = 0; i < 4; i++)
#pragma unroll
            for (int j = 0; j < 4; j++)
                P[(tq * 4 + i) * PPAD + c0 + td * 4 + j] = __fmul_rn(s[i][j], 0.125f);
    }
    __syncthreads();

    // ---- rowmax (exact; order-free) ----
    {
        int r = tid >> 2, c4 = tid & 3;
        float m = -3.402823466e38f;
        for (int k = c4; k < 512; k += 4) m = fmaxf(m, P[r * PPAD + k]);
        KV[tid] = m;
        __syncthreads();
        if (tid < 64)
            Mrow[tid] = fmaxf(fmaxf(KV[tid * 4 + 0], KV[tid * 4 + 1]),
                              fmaxf(KV[tid * 4 + 2], KV[tid * 4 + 3]));
        __syncthreads();
    }

    // ---- exp ----
    {
        int r = tid >> 2, c4 = tid & 3;
        float m = Mrow[r];
        for (int k = c4; k < 512; k += 4)
            P[r * PPAD + k] = expf(__fsub_rn(P[r * PPAD + k], m));
    }
    __syncthreads();

    // ---- row sum (validated tree) ----
    if (tid < 64) {
        const float* row = P + tid * PPAD;
        Srow[tid] = xla_tree512([&](int i) { return row[i]; });
    }
    __syncthreads();

    // ---- divide: w = e / sum ----
    for (int idx = tid; idx < 64 * 512; idx += 256) {
        int r = idx >> 9, k = idx & 511;
        P[r * PPAD + k] = __fdiv_rn(P[r * PPAD + k], Srow[r]);
    }

    // ---- ctx = w @ V: K=512 -> 2 kc-panels of 256, left-assoc fold (validated) ----
    float OT[4][4], OP[4][4];
#pragma unroll
    for (int i = 0; i < 4; i++)
#pragma unroll
        for (int j = 0; j < 4; j++) { OT[i][j] = 0.f; OP[i][j] = 0.f; }

    for (int c0 = 0; c0 < SS; c0 += 64) {
        __syncthreads();
        for (int f = tid; f < 64 * 16; f += 256) {
            int r = f >> 4, c4 = (f & 15) << 2;
            const float* p = base + (size_t)(c0 + r) * (3 * DD) + hoff + c4 + 2 * DD; // V
            float4 vv = *(const float4*)p;
            KV[r * QPAD + c4] = vv.x; KV[r * QPAD + c4 + 1] = vv.y;
            KV[r * QPAD + c4 + 2] = vv.z; KV[r * QPAD + c4 + 3] = vv.w;
        }
        __syncthreads();
#pragma unroll 8
        for (int k = 0; k < 64; k++) {
            float pv[4], vv[4];
#pragma unroll
            for (int i = 0; i < 4; i++) pv[i] = P[(tq * 4 + i) * PPAD + c0 + k];
#pragma unroll
            for (int j = 0; j < 4; j++) vv[j] = KV[k * QPAD + td * 4 + j];
#pragma unroll
            for (int i = 0; i < 4; i++)
#pragma unroll
                for (int j = 0; j < 4; j++) OP[i][j] = fmaf(pv[i], vv[j], OP[i][j]);
        }
        if (((c0 + 64) & (KC - 1)) == 0) {
#pragma unroll
            for (int i = 0; i < 4; i++)
#pragma unroll
                for (int j = 0; j < 4; j++) {
                    OT[i][j] = __fadd_rn(OT[i][j], OP[i][j]);
                    OP[i][j] = 0.f;
                }
        }
    }

#pragma unroll
    for (int i = 0; i < 4; i++) {
        size_t row = (size_t)(b * SS + q0 + tq * 4 + i) * DD + hoff;
#pragma unroll
        for (int j = 0; j < 4; j++) ctx[row + td * 4 + j] = OT[i][j];
    }
}

// ---------------- layernorm (unchanged numerics, validated) ----------------
__global__ __launch_bounds__(256)
void ln_kernel(const float* __restrict__ in, float* __restrict__ out,
               const float* __restrict__ gs, const float* __restrict__ gb) {
    int row = blockIdx.x * 256 + threadIdx.x;
    if (row >= MM) return;
    const float* x = in + (size_t)row * DD;

    float s = xla_tree512([&](int i) { return x[i]; });
    float mean = __fmul_rn(s, 1.0f / 512.0f);

    float q = xla_tree512([&](int i) {
        float d = __fsub_rn(x[i], mean);
        return __fmul_rn(d, d);
    });
    float var = __fmul_rn(q, 1.0f / 512.0f);
    float r = rsqrtf(__fadd_rn(var, 1e-5f));

    float* o = out + (size_t)row * DD;
#pragma unroll 4
    for (int c = 0; c < DD; c++) {
        float d = __fsub_rn(x[c], mean);
        o[c] = __fadd_rn(__fmul_rn(__fmul_rn(d, r), gs[c]), gb[c]);
    }
}

// ---------------- triad resonance ----------------
__global__ void zero_kernel() {
    int i = blockIdx.x * blockDim.x + threadIdx.x;
    if (i < 65536) g_h1[i] = 0u;
    if (i < 131072) ((unsigned*)g_h2)[i] = 0u;
}

__global__ __launch_bounds__(256)
void ss1_kernel(const float* __restrict__ x) {
    double acc = 0.0;
    for (int i = blockIdx.x * blockDim.x + threadIdx.x; i < NTOT; i += gridDim.x * blockDim.x) {
        double v = (double)x[i];
        acc = fma(v, v, acc);
    }
#pragma unroll
    for (int o = 16; o; o >>= 1) acc += __shfl_xor_sync(0xffffffffu, acc, o);
    __shared__ double sm[8];
    if ((threadIdx.x & 31) == 0) sm[threadIdx.x >> 5] = acc;
    __syncthreads();
    if (threadIdx.x == 0) {
        double t = 0.0;
        for (int w = 0; w < 8; w++) t += sm[w];
        g_part[blockIdx.x] = t;
    }
}

__global__ __launch_bounds__(256)
void ss2_kernel() {
    int tid = threadIdx.x;
    double a = ((g_part[tid] + g_part[tid + 256]) + (g_part[tid + 512] + g_part[tid + 768]));
#pragma unroll
    for (int o = 16; o; o >>= 1) a += __shfl_xor_sync(0xffffffffu, a, o);
    __shared__ double sm[8];
    if ((tid & 31) == 0) sm[tid >> 5] = a;
    __syncthreads();
    if (tid == 0) {
        double t = 0.0;
        for (int w = 0; w < 8; w++) t += sm[w];
        g_sumsq = t;
    }
}

// g per element (validated): bits identical; denom hoisted once per thread.
__device__ __forceinline__ float triad_g_d(float h, float denom) {
    return __fmul_rn(__fdiv_rn(h, denom), 2048.0f);
}
__device__ __forceinline__ float triad_denom() {
    float norm = (float)sqrt(g_sumsq);
    return __fadd_rn(norm, 1e-8f);
}

__global__ __launch_bounds__(256)
void hist_hi_kernel(const float* __restrict__ x) {
    const float denom = triad_denom();
    for (int i = blockIdx.x * blockDim.x + threadIdx.x; i < NTOT; i += gridDim.x * blockDim.x) {
        unsigned bits = __float_as_uint(triad_g_d(x[i], denom)) & 0x7fffffffu;
        atomicAdd(&g_h1[bits >> 16], 1u);
    }
}

__global__ __launch_bounds__(256)
void select_hi_kernel() {
    __shared__ unsigned sm[256], pref[256];
    int tid = threadIdx.x;
    int base = tid << 8;
    unsigned local = 0;
    for (int b = 0; b < 256; b++) local += g_h1[base + b];
    sm[tid] = local;
    __syncthreads();
    if (tid == 0) { unsigned c = 0; for (int i = 0; i < 256; i++) { pref[i] = c; c += sm[i]; } }
    __syncthreads();
    unsigned cum = pref[tid];
    for (int b = 0; b < 256; b++) {
        unsigned c = g_h1[base + b];
        if (c) {
            if (K0RANK >= cum && K0RANK < cum + c) { g_sel[0] = (unsigned)(base + b); g_sel[1] = cum; }
            if (K1RANK >= cum && K1RANK < cum + c) { g_sel[2] = (unsigned)(base + b); g_sel[3] = cum; }
        }
        cum += c;
    }
}

__global__ __launch_bounds__(256)
void hist_lo_kernel(const float* __restrict__ x) {
    const float denom = triad_denom();
    unsigned b0 = g_sel[0], b1 = g_sel[2];
    for (int i = blockIdx.x * blockDim.x + threadIdx.x; i < NTOT; i += gridDim.x * blockDim.x) {
        unsigned bits = __float_as_uint(triad_g_d(x[i], denom)) & 0x7fffffffu;
        unsigned hi = bits >> 16;
        if (hi == b0) atomicAdd(&g_h2[0][bits & 0xffffu], 1u);
        else if (hi == b1) atomicAdd(&g_h2[1][bits & 0xffffu], 1u);
    }
}

__global__ __launch_bounds__(256)
void select_lo_kernel() {
    __shared__ unsigned sm[256], pref[256], vb[2];
    int tid = threadIdx.x;
    unsigned b0 = g_sel[0], before0 = g_sel[1], b1 = g_sel[2], before1 = g_sel[3];
    int which1 = (b1 == b0) ? 0 : 1;
    unsigned r0 = K0RANK - before0;
    unsigned r1 = K1RANK - ((which1 == 0) ? before0 : before1);
    for (int pass = 0; pass < 2; pass++) {
        const unsigned* h = g_h2[(pass == 0) ? 0 : which1];
        unsigned target = (pass == 0) ? r0 : r1;
        int base = tid << 8;
        unsigned local = 0;
        for (int b = 0; b < 256; b++) local += h[base + b];
        sm[tid] = local;
        __syncthreads();
        if (tid == 0) { unsigned c = 0; for (int i = 0; i < 256; i++) { pref[i] = c; c += sm[i]; } }
        __syncthreads();
        unsigned cum = pref[tid];
        for (int b = 0; b < 256; b++) {
            unsigned c = h[base + b];
            if (c && target >= cum && target < cum + c) vb[pass] = (unsigned)(base + b);
            cum += c;
        }
        __syncthreads();
    }
    if (tid == 0) {
        float v0 = __uint_as_float((b0 << 16) | vb[0]);
        float v1 = __uint_as_float((((which1 == 0) ? b0 : b1) << 16) | vb[1]);
        // JAX: low*(1-frac) + high*frac, frac=0.25, all f32
        g_thr = __fadd_rn(__fmul_rn(v0, 0.75f), __fmul_rn(v1, 0.25f));
    }
}

__global__ __launch_bounds__(256)
void apply_kernel(float* __restrict__ x, float da, float db) {
    const float denom = triad_denom();
    float thr = g_thr;
    for (int i = blockIdx.x * blockDim.x + threadIdx.x; i < NTOT; i += gridDim.x * blockDim.x) {
        float g = triad_g_d(x[i], denom);
        x[i] = (fabsf(g) > thr) ? __fmul_rn(__fmul_rn(g, da), db) : 0.0f;
    }
}

// ---------------- host launcher ----------------
extern "C" void kernel_launch(void* const* d_in, const int* in_sizes, int n_in,
                              void* d_out, int out_size) {
    const int*   src    = (const int*)  d_in[0];
    const float* emb    = (const float*)d_in[1];
    const float* pos    = (const float*)d_in[2];
    const float* qkv_w  = (const float*)d_in[3];
    const float* qkv_b  = (const float*)d_in[4];
    const float* attn_ow= (const float*)d_in[5];
    const float* attn_ob= (const float*)d_in[6];
    const float* ln1_s  = (const float*)d_in[7];
    const float* ln1_b  = (const float*)d_in[8];
    const float* ln2_s  = (const float*)d_in[9];
    const float* ln2_b  = (const float*)d_in[10];
    const float* ff1_w  = (const float*)d_in[11];
    const float* ff1_b  = (const float*)d_in[12];
    const float* ff2_w  = (const float*)d_in[13];
    const float* ff2_b  = (const float*)d_in[14];
    const float* head_w = (const float*)d_in[15];
    const float* head_b = (const float*)d_in[16];
    float* out = (float*)d_out;

    float* x_p;   cudaGetSymbolAddress((void**)&x_p,   g_x);
    float* qkv_p; cudaGetSymbolAddress((void**)&qkv_p, g_qkv);
    float* ctx_p; cudaGetSymbolAddress((void**)&ctx_p, g_ctx);
    float* tmp_p; cudaGetSymbolAddress((void**)&tmp_p, g_tmp);
    float* ff_p;  cudaGetSymbolAddress((void**)&ff_p,  g_ff);

    cudaFuncSetAttribute(attn_kernel, cudaFuncAttributeMaxDynamicSharedMemorySize, ATTN_SMEM_BYTES);

    const float sqrtD = (float)sqrt(512.0);
    const float dampA = (float)pow(0.99, 1.0 / 6.0);

    embed_kernel<<<(NTOT + 255) / 256, 256>>>(src, emb, pos, x_p, sqrtD);

    for (int i = 0; i < LL; i++) {
        const float* qw  = qkv_w   + (size_t)i * 3 * DD * DD;
        const float* qb  = qkv_b   + (size_t)i * 3 * DD;
        const float* ow  = attn_ow + (size_t)i * DD * DD;
        const float* ob  = attn_ob + (size_t)i * DD;
        const float* f1w = ff1_w   + (size_t)i * FF * DD;
        const float* f1b = ff1_b   + (size_t)i * FF;
        const float* f2w = ff2_w   + (size_t)i * DD * FF;
        const float* f2b = ff2_b   + (size_t)i * DD;

        gemm_kernel<0, 0, false><<<dim3(12, 64), 256>>>(x_p, qw, qb, nullptr, qkv_p, MM, 3 * DD, DD);
        attn_kernel<<<dim3(SS / 64, HH, BB), 256, ATTN_SMEM_BYTES>>>(qkv_p, ctx_p);
        gemm_kernel<0, 1, false><<<dim3(4, 64), 256>>>(ctx_p, ow, ob, x_p, tmp_p, MM, DD, DD);
        ln_kernel<<<MM / 256, 256>>>(tmp_p, x_p, ln1_s + (size_t)i * DD, ln1_b + (size_t)i * DD);
        gemm_kernel<1, 0, false><<<dim3(16, 64), 256>>>(x_p, f1w, f1b, nullptr, ff_p, MM, FF, DD);
        gemm_kernel<0, 2, false><<<dim3(4, 64), 256>>>(ff_p, f2w, f2b, x_p, tmp_p, MM, DD, FF);
        ln_kernel<<<MM / 256, 256>>>(tmp_p, x_p, ln2_s + (size_t)i * DD, ln2_b + (size_t)i * DD);

        zero_kernel<<<512, 256>>>();
        ss1_kernel<<<1024, 256>>>(x_p);
        ss2_kernel<<<1, 256>>>();
        hist_hi_kernel<<<4096, 256>>>(x_p);
        select_hi_kernel<<<1, 256>>>();
        hist_lo_kernel<<<4096, 256>>>(x_p);
        select_lo_kernel<<<1, 256>>>();
        float dampB = (float)pow(0.99, (double)i / 6.0);
        apply_kernel<<<4096, 256>>>(x_p, dampA, dampB);
    }

    gemm_kernel<0, 0, true><<<dim3((VV + 127) / 128, 64), 256>>>(x_p, head_w, head_b, nullptr, out, MM, VV, DD);
}

// round 17
// speedup vs baseline: 1.0971x; 1.0304x over previous
#include <cuda_runtime.h>
#include <math.h>

// Problem constants
#define BB 16
#define SS 512
#define DD 512
#define HH 8
#define HD 64
#define LL 6
#define FF 2048
#define VV 10000
#define MM (BB*SS)          // 8192 rows
#define NTOT (MM*DD)        // 4194304
#define K0RANK 3145727u     // floor(0.75*(NTOT-1))
#define K1RANK 3145728u
#define KC 256              // Eigen gebp kc panel size (VALIDATED R15)

// ---------------- device scratch ----------------
__device__ float g_x[NTOT];
__device__ float g_qkv[MM*3*DD];
__device__ float g_ctx[NTOT];
__device__ float g_tmp[NTOT];
__device__ float g_ff[MM*FF];
__device__ double g_part[1024];
__device__ double g_sumsq;
__device__ unsigned g_h1[65536];
__device__ unsigned g_h2[2][65536];
__device__ unsigned g_sel[4];
__device__ float g_thr;

// ---------------- embedding ----------------
__global__ void embed_kernel(const int* __restrict__ src, const float* __restrict__ emb,
                             const float* __restrict__ pos, float* __restrict__ x, float sqrtD) {
    int i = blockIdx.x * blockDim.x + threadIdx.x;
    if (i >= NTOT) return;
    int t = i >> 9, d = i & 511, s = t & 511;
    float e = emb[(size_t)src[t] * DD + d];
    x[i] = __fadd_rn(__fmul_rn(e, sqrtD), pos[(size_t)s * DD + d]);
}

// ---------------- GEMM: C[M,N] = A[M,K] * W[N,K]^T (+bias,+res,relu) ----------------
// NUMERICS FROZEN (validated R15/R16): per output, serial ascending-k FMA in
// kc=256 panels, left-assoc panel folds. Scheduling: 128x64 tiles, 8x4/thread,
// double-buffered SMEM, one barrier per k-tile, 2 CTAs/SM.
// RESMODE 0: acc+bias ; 1: (res+acc)+bias ; 2: res+(acc+bias)
template<int RELU, int RESMODE, bool BOUND>
__global__ __launch_bounds__(256, 2)
void gemm_kernel(const float* __restrict__ A, const float* __restrict__ W,
                 const float* __restrict__ bias, const float* __restrict__ R,
                 float* __restrict__ C, int M, int N, int K) {
    __shared__ float As[2][16][132];
    __shared__ float Bs[2][16][68];
    const int tid = threadIdx.x;
    const int row0 = blockIdx.y * 128;
    const int col0 = blockIdx.x * 64;
    const int ty = tid >> 4, tx = tid & 15;   // rows ty*8..+7, cols tx*4..+3
    const int lr = tid >> 2;                  // 0..63
    const int lc = (tid & 3) << 2;            // 0,4,8,12

    float accT[8][4], accP[8][4];
#pragma unroll
    for (int i = 0; i < 8; i++)
#pragma unroll
        for (int j = 0; j < 4; j++) { accT[i][j] = 0.f; accP[i][j] = 0.f; }

    float4 ra0, ra1, rb0;

    auto gload = [&](int kt) {
        ra0 = *(const float4*)(A + (size_t)(row0 + lr) * K + kt + lc);
        ra1 = *(const float4*)(A + (size_t)(row0 + 64 + lr) * K + kt + lc);
        int gr = col0 + lr;
        rb0 = (!BOUND || gr < N) ? *(const float4*)(W + (size_t)gr * K + kt + lc)
                                 : make_float4(0.f, 0.f, 0.f, 0.f);
    };
    auto stage = [&](int buf) {
        As[buf][lc + 0][lr] = ra0.x; As[buf][lc + 1][lr] = ra0.y;
        As[buf][lc + 2][lr] = ra0.z; As[buf][lc + 3][lr] = ra0.w;
        As[buf][lc + 0][64 + lr] = ra1.x; As[buf][lc + 1][64 + lr] = ra1.y;
        As[buf][lc + 2][64 + lr] = ra1.z; As[buf][lc + 3][64 + lr] = ra1.w;
        Bs[buf][lc + 0][lr] = rb0.x; Bs[buf][lc + 1][lr] = rb0.y;
        Bs[buf][lc + 2][lr] = rb0.z; Bs[buf][lc + 3][lr] = rb0.w;
    };

    gload(0);
    stage(0);
    __syncthreads();

    const int NT = K >> 4;
    for (int t = 0; t < NT; t++) {
        const int cur = t & 1;
        if (t + 1 < NT) gload((t + 1) << 4);
#pragma unroll
        for (int k = 0; k < 16; k++) {
            float a[8], b[4];
#pragma unroll
            for (int i = 0; i < 8; i++) a[i] = As[cur][k][ty * 8 + i];
#pragma unroll
            for (int j = 0; j < 4; j++) b[j] = Bs[cur][k][tx * 4 + j];
#pragma unroll
            for (int i = 0; i < 8; i++)
#pragma unroll
                for (int j = 0; j < 4; j++) accP[i][j] = fmaf(a[i], b[j], accP[i][j]);
        }
        if (t + 1 < NT) stage(cur ^ 1);
        __syncthreads();
        if ((((t + 1) << 4) & (KC - 1)) == 0) {
#pragma unroll
            for (int i = 0; i < 8; i++)
#pragma unroll
                for (int j = 0; j < 4; j++) {
                    accT[i][j] = __fadd_rn(accT[i][j], accP[i][j]);
                    accP[i][j] = 0.f;
                }
        }
    }

#pragma unroll
    for (int i = 0; i < 8; i++) {
        int r = row0 + ty * 8 + i;
#pragma unroll
        for (int j = 0; j < 4; j++) {
            int c = col0 + tx * 4 + j;
            if (BOUND && c >= N) continue;
            float v;
            if (RESMODE == 0) {
                v = __fadd_rn(accT[i][j], bias[c]);
            } else if (RESMODE == 1) {
                v = __fadd_rn(__fadd_rn(R[(size_t)r * N + c], accT[i][j]), bias[c]);
            } else {
                v = __fadd_rn(R[(size_t)r * N + c], __fadd_rn(accT[i][j], bias[c]));
            }
            if (RELU) v = fmaxf(v, 0.f);
            C[(size_t)r * N + c] = v;
        }
    }
}

// ---------------- row-reduce tree (validated R15 bracketing) ----------------
template<typename F>
__device__ __forceinline__ float xla_tree512(F val) {
    float S[8];
#pragma unroll
    for (int w = 0; w < 8; w++) {
        int base = w * 64;
        float p[32];
#pragma unroll
        for (int t = 0; t < 32; t++)
            p[t] = __fadd_rn(val(base + 2 * t), val(base + 2 * t + 1));
#pragma unroll
        for (int t = 0; t < 16; t++) p[t] = __fadd_rn(p[t], p[t + 16]);
#pragma unroll
        for (int t = 0; t < 8; t++)  p[t] = __fadd_rn(p[t], p[t + 8]);
#pragma unroll
        for (int t = 0; t < 4; t++)  p[t] = __fadd_rn(p[t], p[t + 4]);
        float d0 = __fadd_rn(p[0], p[2]);
        float d1 = __fadd_rn(p[1], p[3]);
        S[w] = __fadd_rn(d0, d1);
    }
    float e0 = __fadd_rn(S[0], S[4]);
    float e1 = __fadd_rn(S[1], S[5]);
    float e2 = __fadd_rn(S[2], S[6]);
    float e3 = __fadd_rn(S[3], S[7]);
    return __fadd_rn(__fadd_rn(e0, e2), __fadd_rn(e1, e3));
}

// ---------------- attention: 32-row q-tiles for 2 CTAs/SM ----------------
// Numerics identical: scores serial k=0..63; ctx serial k in two 256-panels,
// left-assoc fold; same tree sum, exp, divide, rowmax.
#define QPAD 68
#define PPAD 513
#define A2_Q   0                    // 32*68 = 2176
#define A2_KV  2176                 // 64*68 = 4352
#define A2_P   6528                 // 32*513 = 16416
#define A2_M   22944                // 32
#define A2_S   22976                // 32
#define ATTN_SMEM_BYTES (23008*4)   // 92032 B

__global__ __launch_bounds__(256)
void attn_kernel(const float* __restrict__ qkv, float* __restrict__ ctx) {
    extern __shared__ float sm[];
    float* Qs = sm + A2_Q;
    float* KV = sm + A2_KV;
    float* P  = sm + A2_P;
    float* Mrow = sm + A2_M;
    float* Srow = sm + A2_S;

    const int tid = threadIdx.x;
    const int b = blockIdx.z, h = blockIdx.y, q0 = blockIdx.x * 32;
    const float* base = qkv + (size_t)b * SS * (3 * DD);
    const int hoff = h * HD;
    const int tq = tid >> 4, td = tid & 15;   // rows tq*2..+1, cols td*4..+3

    // load Q tile [32][64]
    for (int f = tid; f < 32 * 16; f += 256) {
        int r = f >> 4, c4 = (f & 15) << 2;
        float4 v = *(const float4*)(base + (size_t)(q0 + r) * (3 * DD) + hoff + c4);
        Qs[r * QPAD + c4] = v.x; Qs[r * QPAD + c4 + 1] = v.y;
        Qs[r * QPAD + c4 + 2] = v.z; Qs[r * QPAD + c4 + 3] = v.w;
    }

    // ---- scores t=(q.k)*0.125 (serial k FMA; /8 exact) ----
    for (int c0 = 0; c0 < SS; c0 += 64) {
        __syncthreads();
        for (int f = tid; f < 64 * 16; f += 256) {
            int r = f >> 4, c4 = (f & 15) << 2;
            const float* p = base + (size_t)(c0 + r) * (3 * DD) + hoff + c4 + DD; // K
            float4 kv = *(const float4*)p;
            KV[r * QPAD + c4] = kv.x; KV[r * QPAD + c4 + 1] = kv.y;
            KV[r * QPAD + c4 + 2] = kv.z; KV[r * QPAD + c4 + 3] = kv.w;
        }
        __syncthreads();
        float s[2][4];
#pragma unroll
        for (int i = 0; i < 2; i++)
#pragma unroll
            for (int j = 0; j < 4; j++) s[i][j] = 0.f;
#pragma unroll
        for (int d = 0; d < 64; d++) {
            float qa[2], kb[4];
#pragma unroll
            for (int i = 0; i < 2; i++) qa[i] = Qs[(tq * 2 + i) * QPAD + d];
#pragma unroll
            for (int j = 0; j < 4; j++) kb[j] = KV[(td * 4 + j) * QPAD + d];
#pragma unroll
            for (int i = 0; i < 2; i++)
#pragma unroll
                for (int j = 0; j < 4; j++) s[i][j] = fmaf(qa[i], kb[j], s[i][j]);
        }
#pragma unroll
        for (int i = 0; i < 2; i++)
#pragma unroll
            for (int j = 0; j < 4; j++)
                P[(tq * 2 + i) * PPAD + c0 + td * 4 + j] = __fmul_rn(s[i][j], 0.125f);
    }
    __syncthreads();

    // ---- rowmax (exact; order-free): 8 threads per row ----
    {
        int r = tid >> 3, c8 = tid & 7;
        float m = -3.402823466e38f;
        for (int k = c8; k < 512; k += 8) m = fmaxf(m, P[r * PPAD + k]);
        KV[tid] = m;
        __syncthreads();
        if (tid < 32) {
            float mm = KV[tid * 8];
            for (int j = 1; j < 8; j++) mm = fmaxf(mm, KV[tid * 8 + j]);
            Mrow[tid] = mm;
        }
        __syncthreads();
    }

    // ---- exp ----
    {
        int r = tid >> 3, c8 = tid & 7;
        float m = Mrow[r];
        for (int k = c8; k < 512; k += 8)
            P[r * PPAD + k] = expf(__fsub_rn(P[r * PPAD + k], m));
    }
    __syncthreads();

    // ---- row sum (validated tree) ----
    if (tid < 32) {
        const float* row = P + tid * PPAD;
        Srow[tid] = xla_tree512([&](int i) { return row[i]; });
    }
    __syncthreads();

    // ---- divide: w = e / sum ----
    for (int idx = tid; idx < 32 * 512; idx += 256) {
        int r = idx >> 9, k = idx & 511;
        P[r * PPAD + k] = __fdiv_rn(P[r * PPAD + k], Srow[r]);
    }

    // ---- ctx = w @ V: two 256-panels, left-assoc fold (validated) ----
    float OT[2][4], OP[2][4];
#pragma unroll
    for (int i = 0; i < 2; i++)
#pragma unroll
        for (int j = 0; j < 4; j++) { OT[i][j] = 0.f; OP[i][j] = 0.f; }

    for (int c0 = 0; c0 < SS; c0 += 64) {
        __syncthreads();
        for (int f = tid; f < 64 * 16; f += 256) {
            int r = f >> 4, c4 = (f & 15) << 2;
            const float* p = base + (size_t)(c0 + r) * (3 * DD) + hoff + c4 + 2 * DD; // V
            float4 vv = *(const float4*)p;
            KV[r * QPAD + c4] = vv.x; KV[r * QPAD + c4 + 1] = vv.y;
            KV[r * QPAD + c4 + 2] = vv.z; KV[r * QPAD + c4 + 3] = vv.w;
        }
        __syncthreads();
#pragma unroll 8
        for (int k = 0; k < 64; k++) {
            float pv[2], vv[4];
#pragma unroll
            for (int i = 0; i < 2; i++) pv[i] = P[(tq * 2 + i) * PPAD + c0 + k];
#pragma unroll
            for (int j = 0; j < 4; j++) vv[j] = KV[k * QPAD + td * 4 + j];
#pragma unroll
            for (int i = 0; i < 2; i++)
#pragma unroll
                for (int j = 0; j < 4; j++) OP[i][j] = fmaf(pv[i], vv[j], OP[i][j]);
        }
        if (((c0 + 64) & (KC - 1)) == 0) {
#pragma unroll
            for (int i = 0; i < 2; i++)
#pragma unroll
                for (int j = 0; j < 4; j++) {
                    OT[i][j] = __fadd_rn(OT[i][j], OP[i][j]);
                    OP[i][j] = 0.f;
                }
        }
    }

#pragma unroll
    for (int i = 0; i < 2; i++) {
        size_t row = (size_t)(b * SS + q0 + tq * 2 + i) * DD + hoff;
#pragma unroll
        for (int j = 0; j < 4; j++) ctx[row + td * 4 + j] = OT[i][j];
    }
}

// ---------------- layernorm (validated numerics) ----------------
__global__ __launch_bounds__(256)
void ln_kernel(const float* __restrict__ in, float* __restrict__ out,
               const float* __restrict__ gs, const float* __restrict__ gb) {
    int row = blockIdx.x * 256 + threadIdx.x;
    if (row >= MM) return;
    const float* x = in + (size_t)row * DD;

    float s = xla_tree512([&](int i) { return x[i]; });
    float mean = __fmul_rn(s, 1.0f / 512.0f);

    float q = xla_tree512([&](int i) {
        float d = __fsub_rn(x[i], mean);
        return __fmul_rn(d, d);
    });
    float var = __fmul_rn(q, 1.0f / 512.0f);
    float r = rsqrtf(__fadd_rn(var, 1e-5f));

    float* o = out + (size_t)row * DD;
#pragma unroll 4
    for (int c = 0; c < DD; c++) {
        float d = __fsub_rn(x[c], mean);
        o[c] = __fadd_rn(__fmul_rn(__fmul_rn(d, r), gs[c]), gb[c]);
    }
}

// ---------------- triad resonance ----------------
__global__ void zero_kernel() {
    int i = blockIdx.x * blockDim.x + threadIdx.x;
    if (i < 65536) g_h1[i] = 0u;
    if (i < 131072) ((unsigned*)g_h2)[i] = 0u;
}

__global__ __launch_bounds__(256)
void ss1_kernel(const float* __restrict__ x) {
    double acc = 0.0;
    for (int i = blockIdx.x * blockDim.x + threadIdx.x; i < NTOT; i += gridDim.x * blockDim.x) {
        double v = (double)x[i];
        acc = fma(v, v, acc);
    }
#pragma unroll
    for (int o = 16; o; o >>= 1) acc += __shfl_xor_sync(0xffffffffu, acc, o);
    __shared__ double sm[8];
    if ((threadIdx.x & 31) == 0) sm[threadIdx.x >> 5] = acc;
    __syncthreads();
    if (threadIdx.x == 0) {
        double t = 0.0;
        for (int w = 0; w < 8; w++) t += sm[w];
        g_part[blockIdx.x] = t;
    }
}

__global__ __launch_bounds__(256)
void ss2_kernel() {
    int tid = threadIdx.x;
    double a = ((g_part[tid] + g_part[tid + 256]) + (g_part[tid + 512] + g_part[tid + 768]));
#pragma unroll
    for (int o = 16; o; o >>= 1) a += __shfl_xor_sync(0xffffffffu, a, o);
    __shared__ double sm[8];
    if ((tid & 31) == 0) sm[tid >> 5] = a;
    __syncthreads();
    if (tid == 0) {
        double t = 0.0;
        for (int w = 0; w < 8; w++) t += sm[w];
        g_sumsq = t;
    }
}

// g per element (validated bits); denom hoisted once per thread.
__device__ __forceinline__ float triad_g_d(float h, float denom) {
    return __fmul_rn(__fdiv_rn(h, denom), 2048.0f);
}
__device__ __forceinline__ float triad_denom() {
    float norm = (float)sqrt(g_sumsq);
    return __fadd_rn(norm, 1e-8f);
}

__global__ __launch_bounds__(256)
void hist_hi_kernel(const float* __restrict__ x) {
    const float denom = triad_denom();
    for (int i = blockIdx.x * blockDim.x + threadIdx.x; i < NTOT; i += gridDim.x * blockDim.x) {
        unsigned bits = __float_as_uint(triad_g_d(x[i], denom)) & 0x7fffffffu;
        atomicAdd(&g_h1[bits >> 16], 1u);
    }
}

__global__ __launch_bounds__(256)
void select_hi_kernel() {
    __shared__ unsigned sm[256], pref[256];
    int tid = threadIdx.x;
    int base = tid << 8;
    unsigned local = 0;
    for (int b = 0; b < 256; b++) local += g_h1[base + b];
    sm[tid] = local;
    __syncthreads();
    if (tid == 0) { unsigned c = 0; for (int i = 0; i < 256; i++) { pref[i] = c; c += sm[i]; } }
    __syncthreads();
    unsigned cum = pref[tid];
    for (int b = 0; b < 256; b++) {
        unsigned c = g_h1[base + b];
        if (c) {
            if (K0RANK >= cum && K0RANK < cum + c) { g_sel[0] = (unsigned)(base + b); g_sel[1] = cum; }
            if (K1RANK >= cum && K1RANK < cum + c) { g_sel[2] = (unsigned)(base + b); g_sel[3] = cum; }
        }
        cum += c;
    }
}

__global__ __launch_bounds__(256)
void hist_lo_kernel(const float* __restrict__ x) {
    const float denom = triad_denom();
    unsigned b0 = g_sel[0], b1 = g_sel[2];
    for (int i = blockIdx.x * blockDim.x + threadIdx.x; i < NTOT; i += gridDim.x * blockDim.x) {
        unsigned bits = __float_as_uint(triad_g_d(x[i], denom)) & 0x7fffffffu;
        unsigned hi = bits >> 16;
        if (hi == b0) atomicAdd(&g_h2[0][bits & 0xffffu], 1u);
        else if (hi == b1) atomicAdd(&g_h2[1][bits & 0xffffu], 1u);
    }
}

__global__ __launch_bounds__(256)
void select_lo_kernel() {
    __shared__ unsigned sm[256], pref[256], vb[2];
    int tid = threadIdx.x;
    unsigned b0 = g_sel[0], before0 = g_sel[1], b1 = g_sel[2], before1 = g_sel[3];
    int which1 = (b1 == b0) ? 0 : 1;
    unsigned r0 = K0RANK - before0;
    unsigned r1 = K1RANK - ((which1 == 0) ? before0 : before1);
    for (int pass = 0; pass < 2; pass++) {
        const unsigned* h = g_h2[(pass == 0) ? 0 : which1];
        unsigned target = (pass == 0) ? r0 : r1;
        int base = tid << 8;
        unsigned local = 0;
        for (int b = 0; b < 256; b++) local += h[base + b];
        sm[tid] = local;
        __syncthreads();
        if (tid == 0) { unsigned c = 0; for (int i = 0; i < 256; i++) { pref[i] = c; c += sm[i]; } }
        __syncthreads();
        unsigned cum = pref[tid];
        for (int b = 0; b < 256; b++) {
            unsigned c = h[base + b];
            if (c && target >= cum && target < cum + c) vb[pass] = (unsigned)(base + b);
            cum += c;
        }
        __syncthreads();
    }
    if (tid == 0) {
        float v0 = __uint_as_float((b0 << 16) | vb[0]);
        float v1 = __uint_as_float((((which1 == 0) ? b0 : b1) << 16) | vb[1]);
        g_thr = __fadd_rn(__fmul_rn(v0, 0.75f), __fmul_rn(v1, 0.25f));
    }
}

__global__ __launch_bounds__(256)
void apply_kernel(float* __restrict__ x, float da, float db) {
    const float denom = triad_denom();
    float thr = g_thr;
    for (int i = blockIdx.x * blockDim.x + threadIdx.x; i < NTOT; i += gridDim.x * blockDim.x) {
        float g = triad_g_d(x[i], denom);
        x[i] = (fabsf(g) > thr) ? __fmul_rn(__fmul_rn(g, da), db) : 0.0f;
    }
}

// ---------------- host launcher ----------------
extern "C" void kernel_launch(void* const* d_in, const int* in_sizes, int n_in,
                              void* d_out, int out_size) {
    const int*   src    = (const int*)  d_in[0];
    const float* emb    = (const float*)d_in[1];
    const float* pos    = (const float*)d_in[2];
    const float* qkv_w  = (const float*)d_in[3];
    const float* qkv_b  = (const float*)d_in[4];
    const float* attn_ow= (const float*)d_in[5];
    const float* attn_ob= (const float*)d_in[6];
    const float* ln1_s  = (const float*)d_in[7];
    const float* ln1_b  = (const float*)d_in[8];
    const float* ln2_s  = (const float*)d_in[9];
    const float* ln2_b  = (const float*)d_in[10];
    const float* ff1_w  = (const float*)d_in[11];
    const float* ff1_b  = (const float*)d_in[12];
    const float* ff2_w  = (const float*)d_in[13];
    const float* ff2_b  = (const float*)d_in[14];
    const float* head_w = (const float*)d_in[15];
    const float* head_b = (const float*)d_in[16];
    float* out = (float*)d_out;

    float* x_p;   cudaGetSymbolAddress((void**)&x_p,   g_x);
    float* qkv_p; cudaGetSymbolAddress((void**)&qkv_p, g_qkv);
    float* ctx_p; cudaGetSymbolAddress((void**)&ctx_p, g_ctx);
    float* tmp_p; cudaGetSymbolAddress((void**)&tmp_p, g_tmp);
    float* ff_p;  cudaGetSymbolAddress((void**)&ff_p,  g_ff);

    cudaFuncSetAttribute(attn_kernel, cudaFuncAttributeMaxDynamicSharedMemorySize, ATTN_SMEM_BYTES);

    const float sqrtD = (float)sqrt(512.0);
    const float dampA = (float)pow(0.99, 1.0 / 6.0);

    embed_kernel<<<(NTOT + 255) / 256, 256>>>(src, emb, pos, x_p, sqrtD);

    for (int i = 0; i < LL; i++) {
        const float* qw  = qkv_w   + (size_t)i * 3 * DD * DD;
        const float* qb  = qkv_b   + (size_t)i * 3 * DD;
        const float* ow  = attn_ow + (size_t)i * DD * DD;
        const float* ob  = attn_ob + (size_t)i * DD;
        const float* f1w = ff1_w   + (size_t)i * FF * DD;
        const float* f1b = ff1_b   + (size_t)i * FF;
        const float* f2w = ff2_w   + (size_t)i * DD * FF;
        const float* f2b = ff2_b   + (size_t)i * DD;

        gemm_kernel<0, 0, false><<<dim3(24, 64), 256>>>(x_p, qw, qb, nullptr, qkv_p, MM, 3 * DD, DD);
        attn_kernel<<<dim3(SS / 32, HH, BB), 256, ATTN_SMEM_BYTES>>>(qkv_p, ctx_p);
        gemm_kernel<0, 1, false><<<dim3(8, 64), 256>>>(ctx_p, ow, ob, x_p, tmp_p, MM, DD, DD);
        ln_kernel<<<MM / 256, 256>>>(tmp_p, x_p, ln1_s + (size_t)i * DD, ln1_b + (size_t)i * DD);
        gemm_kernel<1, 0, false><<<dim3(32, 64), 256>>>(x_p, f1w, f1b, nullptr, ff_p, MM, FF, DD);
        gemm_kernel<0, 2, false><<<dim3(8, 64), 256>>>(ff_p, f2w, f2b, x_p, tmp_p, MM, DD, FF);
        ln_kernel<<<MM / 256, 256>>>(tmp_p, x_p, ln2_s + (size_t)i * DD, ln2_b + (size_t)i * DD);

        zero_kernel<<<512, 256>>>();
        ss1_kernel<<<1024, 256>>>(x_p);
        ss2_kernel<<<1, 256>>>();
        hist_hi_kernel<<<4096, 256>>>(x_p);
        select_hi_kernel<<<1, 256>>>();
        hist_lo_kernel<<<4096, 256>>>(x_p);
        select_lo_kernel<<<1, 256>>>();
        float dampB = (float)pow(0.99, (double)i / 6.0);
        apply_kernel<<<4096, 256>>>(x_p, dampA, dampB);
    }

    gemm_kernel<0, 0, true><<<dim3((VV + 63) / 64, 64), 256>>>(x_p, head_w, head_b, nullptr, out, MM, VV, DD);
}